// round 4
// baseline (speedup 1.0000x reference)
#include <cuda_runtime.h>
#include <cstdint>
#include <cstddef>
#include <math.h>

// Problem constants
#define BB 2
#define NN 2048
#define DD 1024
#define HH 16
#define DHH 64
#define DFF 4096
#define MTOK 4096            // B*N tokens
#define SCORE_SCALE 0.03125f // D^-0.5 = 1/32

// ---------------- Scratch (static device globals; no cudaMalloc allowed) ----
__device__ float g_h[(size_t)MTOK * DD];                  // LN output (reused)
__device__ float g_qkv[(size_t)MTOK * (3 * DD)];          // QKV projection
__device__ float g_kT[(size_t)BB * HH * DHH * NN];        // K^T per head: [z][64][2048]
__device__ float g_scores[(size_t)BB * HH * NN * NN];     // scores / probs (in place)
__device__ float g_attn[(size_t)MTOK * DD];               // attn out, [b*N+n][h*64+dh]
__device__ float g_x1[(size_t)MTOK * DD];                 // x + proj(attn)
__device__ float g_mid[(size_t)MTOK * DFF];               // MLP hidden

__device__ __forceinline__ float gelu_exact(float v) {
    return 0.5f * v * (1.0f + erff(v * 0.70710678118654752f));
}

__device__ __forceinline__ uint32_t tf32_bits(float x) {
    uint32_t u;
    asm("cvt.rna.tf32.f32 %0, %1;" : "=r"(u) : "f"(x));
    return u;
}

__device__ __forceinline__ void mma_tf32(float* c, const uint32_t* a,
                                         const uint32_t* b) {
    asm volatile(
        "mma.sync.aligned.m16n8k8.row.col.f32.tf32.tf32.f32 "
        "{%0,%1,%2,%3}, {%4,%5,%6,%7}, {%8,%9}, {%0,%1,%2,%3};"
        : "+f"(c[0]), "+f"(c[1]), "+f"(c[2]), "+f"(c[3])
        : "r"(a[0]), "r"(a[1]), "r"(a[2]), "r"(a[3]), "r"(b[0]), "r"(b[1]));
}

__device__ __forceinline__ void cp_async16(uint32_t saddr, const void* gptr) {
    asm volatile("cp.async.cg.shared.global [%0], [%1], 16;"
                 :: "r"(saddr), "l"(gptr));
}
__device__ __forceinline__ void cp_commit() {
    asm volatile("cp.async.commit_group;");
}
template <int N>
__device__ __forceinline__ void cp_wait() {
    asm volatile("cp.async.wait_group %0;" :: "n"(N));
}

// ---------------- TF32 tensor-core GEMM with fused epilogue ----------------
// C = A @ B. A row-major [M,K] (lda), B row-major [K,N] (ldb), C [M,N] (ldc).
// Batch via blockIdx.z: ptr += (z>>4)*outer + (z&15)*inner (H=16 split).
// Epilogue order: scores transform (v*scale - gamma[z]*dist[row,col]),
// bias[col], exact GELU, residual[row*ldres+col]. Optional via nullptr/flag.
// 256 threads = 8 warps; warp tile (BM/WARPS_M) x 32; mma m16n8k8 tf32.
// Global->smem via cp.async (raw fp32); tf32 convert at fragment load.
template <int BM, int BN, int BK>
__global__ void __launch_bounds__(256, 2)
tf32gemm_kernel(const float* __restrict__ A, const float* __restrict__ Bm,
                float* __restrict__ C,
                int M, int Ncols, int K, int lda, int ldb, int ldc,
                size_t aOuter, size_t aInner, size_t bOuter, size_t bInner,
                size_t cOuter, size_t cInner,
                const float* __restrict__ bias,
                const float* __restrict__ res, int ldres, int act,
                const float* __restrict__ gamma, const float* __restrict__ dist,
                float scale) {
    constexpr int THREADS = 256;
    constexpr int WARPS_N = BN / 32;           // warps along N (WN = 32)
    constexpr int WARPS_M = 8 / WARPS_N;       // warps along M
    constexpr int WM = BM / WARPS_M;           // rows per warp
    constexpr int MI = WM / 16;                // m16 tiles per warp
    constexpr int APAD = 4;                    // As row stride 20 (conflict-free)
    constexpr int BPAD = 8;                    // Bs row stride BN+8 (conflict-free)

    const int z = blockIdx.z;
    A  += (size_t)(z >> 4) * aOuter + (size_t)(z & 15) * aInner;
    Bm += (size_t)(z >> 4) * bOuter + (size_t)(z & 15) * bInner;
    C  += (size_t)(z >> 4) * cOuter + (size_t)(z & 15) * cInner;

    __shared__ float As[2][BM][BK + APAD];     // row-major fp32
    __shared__ float Bs[2][BK][BN + BPAD];     // k-major rows fp32

    const int tid = threadIdx.x;
    const int wid = tid >> 5;
    const int lane = tid & 31;
    const int grp = lane >> 2;                 // 0..7
    const int qid = lane & 3;                  // 0..3
    const int warp_m0 = (wid % WARPS_M) * WM;
    const int warp_n0 = (wid / WARPS_M) * 32;
    const int m0 = blockIdx.y * BM;
    const int n0 = blockIdx.x * BN;

    float acc[MI][4][4];
#pragma unroll
    for (int i = 0; i < MI; i++)
#pragma unroll
        for (int j = 0; j < 4; j++)
#pragma unroll
            for (int r = 0; r < 4; r++) acc[i][j][r] = 0.0f;

    constexpr int A_V4 = BM * BK / 4;          // 16B chunks per A tile
    constexpr int B_V4 = BK * BN / 4;
    constexpr int A_LD = (A_V4 + THREADS - 1) / THREADS;
    constexpr int B_LD = (B_V4 + THREADS - 1) / THREADS;

    // Per-thread fixed tile coordinates for async copies
    int a_m[A_LD], a_k[A_LD], b_k[B_LD], b_n[B_LD];
#pragma unroll
    for (int u = 0; u < A_LD; u++) {
        int i = tid + u * THREADS;
        a_m[u] = i / (BK / 4);
        a_k[u] = (i % (BK / 4)) * 4;
    }
#pragma unroll
    for (int u = 0; u < B_LD; u++) {
        int i = tid + u * THREADS;
        b_k[u] = i / (BN / 4);
        b_n[u] = (i % (BN / 4)) * 4;
    }

    const int KT = K / BK;

    // ---- async tile loader ----
    auto load_tile = [&](int buf, int k0) {
#pragma unroll
        for (int u = 0; u < A_LD; u++) {
            if (tid + u * THREADS < A_V4) {
                uint32_t sa = (uint32_t)__cvta_generic_to_shared(
                    &As[buf][a_m[u]][a_k[u]]);
                cp_async16(sa, &A[(size_t)(m0 + a_m[u]) * lda + k0 + a_k[u]]);
            }
        }
#pragma unroll
        for (int u = 0; u < B_LD; u++) {
            if (tid + u * THREADS < B_V4) {
                uint32_t sb = (uint32_t)__cvta_generic_to_shared(
                    &Bs[buf][b_k[u]][b_n[u]]);
                cp_async16(sb, &Bm[(size_t)(k0 + b_k[u]) * ldb + n0 + b_n[u]]);
            }
        }
    };

    // ---- Prologue ----
    load_tile(0, 0);
    cp_commit();

    for (int kt = 0; kt < KT; kt++) {
        const int cur = kt & 1;
        const int nxt = cur ^ 1;

        if (kt + 1 < KT) {
            load_tile(nxt, (kt + 1) * BK);   // overlaps compute of tile kt
            cp_commit();
            cp_wait<1>();                    // tile kt complete for this thread
        } else {
            cp_wait<0>();
        }
        __syncthreads();                     // copies visible to all warps

        // ---- Tensor-core compute on current buffer ----
#pragma unroll
        for (int kh = 0; kh < BK; kh += 8) {
            uint32_t af[MI][4];
            uint32_t bf[4][2];
#pragma unroll
            for (int mi = 0; mi < MI; mi++) {
                const int mr = warp_m0 + mi * 16 + grp;
                af[mi][0] = tf32_bits(As[cur][mr][kh + qid]);
                af[mi][1] = tf32_bits(As[cur][mr + 8][kh + qid]);
                af[mi][2] = tf32_bits(As[cur][mr][kh + qid + 4]);
                af[mi][3] = tf32_bits(As[cur][mr + 8][kh + qid + 4]);
            }
#pragma unroll
            for (int ni = 0; ni < 4; ni++) {
                const int nc = warp_n0 + ni * 8 + grp;
                bf[ni][0] = tf32_bits(Bs[cur][kh + qid][nc]);
                bf[ni][1] = tf32_bits(Bs[cur][kh + qid + 4][nc]);
            }
#pragma unroll
            for (int mi = 0; mi < MI; mi++)
#pragma unroll
                for (int ni = 0; ni < 4; ni++)
                    mma_tf32(acc[mi][ni], af[mi], bf[ni]);
        }
        __syncthreads();                     // cur free before kt+1 refills it
    }

    // ---- Epilogue (fragment layout: rows grp/grp+8, col pairs 2*qid) ----
    const float g = (dist != nullptr) ? gamma[z] : 0.0f;
#pragma unroll
    for (int mi = 0; mi < MI; mi++) {
#pragma unroll
        for (int ni = 0; ni < 4; ni++) {
            const int col = n0 + warp_n0 + ni * 8 + 2 * qid;
#pragma unroll
            for (int half = 0; half < 2; half++) {
                const int row = m0 + warp_m0 + mi * 16 + grp + half * 8;
                float2 v = make_float2(acc[mi][ni][half * 2],
                                       acc[mi][ni][half * 2 + 1]);
                if (dist != nullptr) {
                    float2 dd = *reinterpret_cast<const float2*>(
                        &dist[(size_t)row * Ncols + col]);
                    v.x = v.x * scale - g * dd.x;
                    v.y = v.y * scale - g * dd.y;
                }
                if (bias != nullptr) {
                    float2 bb = *reinterpret_cast<const float2*>(&bias[col]);
                    v.x += bb.x; v.y += bb.y;
                }
                if (act) {
                    v.x = gelu_exact(v.x);
                    v.y = gelu_exact(v.y);
                }
                if (res != nullptr) {
                    float2 rr = *reinterpret_cast<const float2*>(
                        &res[(size_t)row * ldres + col]);
                    v.x += rr.x; v.y += rr.y;
                }
                *reinterpret_cast<float2*>(&C[(size_t)row * ldc + col]) = v;
            }
        }
    }
}

// ---------------- LayerNorm: one block per row of 1024 ---------------------
__global__ void ln_kernel(const float* __restrict__ x, const float* __restrict__ w,
                          const float* __restrict__ b, float* __restrict__ o) {
    const int row = blockIdx.x;
    const int t = threadIdx.x; // 256 threads * 4 = 1024 elements
    const float4* xr = reinterpret_cast<const float4*>(x + (size_t)row * DD);
    float4 v = xr[t];
    float s = v.x + v.y + v.z + v.w;
    float q = v.x * v.x + v.y * v.y + v.z * v.z + v.w * v.w;
#pragma unroll
    for (int off = 16; off; off >>= 1) {
        s += __shfl_xor_sync(0xffffffffu, s, off);
        q += __shfl_xor_sync(0xffffffffu, q, off);
    }
    __shared__ float ss[8], qq[8];
    if ((t & 31) == 0) { ss[t >> 5] = s; qq[t >> 5] = q; }
    __syncthreads();
    if (t < 32) {
        s = (t < 8) ? ss[t] : 0.0f;
        q = (t < 8) ? qq[t] : 0.0f;
#pragma unroll
        for (int off = 4; off; off >>= 1) {
            s += __shfl_xor_sync(0xffffffffu, s, off);
            q += __shfl_xor_sync(0xffffffffu, q, off);
        }
        if (t == 0) { ss[0] = s; qq[0] = q; }
    }
    __syncthreads();
    s = ss[0]; q = qq[0];
    const float mu = s * (1.0f / DD);
    const float var = q * (1.0f / DD) - mu * mu;
    const float inv = rsqrtf(var + 1e-5f);
    float4 wv = reinterpret_cast<const float4*>(w)[t];
    float4 bv = reinterpret_cast<const float4*>(b)[t];
    float4 r;
    r.x = (v.x - mu) * inv * wv.x + bv.x;
    r.y = (v.y - mu) * inv * wv.y + bv.y;
    r.z = (v.z - mu) * inv * wv.z + bv.z;
    r.w = (v.w - mu) * inv * wv.w + bv.w;
    reinterpret_cast<float4*>(o + (size_t)row * DD)[t] = r;
}

// ---------------- Per-head K transpose: qkv -> kT[z][64][2048] -------------
__global__ void transpose_k_kernel(const float* __restrict__ qkv,
                                   float* __restrict__ kT) {
    __shared__ float tile[32][33];
    const int z = blockIdx.z;
    const int bb = z >> 4, hh = z & 15;
    const int n0 = blockIdx.x * 32;
    const int d0 = blockIdx.y * 32;
    const int x = threadIdx.x, y = threadIdx.y; // 32 x 8
    for (int yy = y; yy < 32; yy += 8) {
        tile[yy][x] = qkv[(size_t)(bb * NN + n0 + yy) * (3 * DD) + DD +
                          hh * DHH + d0 + x];
    }
    __syncthreads();
    for (int yy = y; yy < 32; yy += 8) {
        kT[((size_t)z * DHH + d0 + yy) * NN + n0 + x] = tile[x][yy];
    }
}

// ---------------- Softmax over rows of 2048 (in place) ---------------------
__global__ void softmax_kernel(float* __restrict__ sc) {
    float* r = sc + ((size_t)blockIdx.y * NN + blockIdx.x) * NN;
    const int t = threadIdx.x; // 256 threads * 8 = 2048
    float4 a = reinterpret_cast<float4*>(r)[t];
    float4 c = reinterpret_cast<float4*>(r)[t + 256];
    float m = fmaxf(fmaxf(fmaxf(a.x, a.y), fmaxf(a.z, a.w)),
                    fmaxf(fmaxf(c.x, c.y), fmaxf(c.z, c.w)));
#pragma unroll
    for (int off = 16; off; off >>= 1)
        m = fmaxf(m, __shfl_xor_sync(0xffffffffu, m, off));
    __shared__ float sm[8];
    if ((t & 31) == 0) sm[t >> 5] = m;
    __syncthreads();
    if (t < 32) {
        m = (t < 8) ? sm[t] : -1e30f;
#pragma unroll
        for (int off = 4; off; off >>= 1)
            m = fmaxf(m, __shfl_xor_sync(0xffffffffu, m, off));
        if (t == 0) sm[0] = m;
    }
    __syncthreads();
    m = sm[0];
    a.x = __expf(a.x - m); a.y = __expf(a.y - m);
    a.z = __expf(a.z - m); a.w = __expf(a.w - m);
    c.x = __expf(c.x - m); c.y = __expf(c.y - m);
    c.z = __expf(c.z - m); c.w = __expf(c.w - m);
    float s = a.x + a.y + a.z + a.w + c.x + c.y + c.z + c.w;
#pragma unroll
    for (int off = 16; off; off >>= 1)
        s += __shfl_xor_sync(0xffffffffu, s, off);
    __shared__ float sw[8];
    if ((t & 31) == 0) sw[t >> 5] = s;
    __syncthreads();
    if (t < 32) {
        s = (t < 8) ? sw[t] : 0.0f;
#pragma unroll
        for (int off = 4; off; off >>= 1)
            s += __shfl_xor_sync(0xffffffffu, s, off);
        if (t == 0) sw[0] = s;
    }
    __syncthreads();
    const float inv = 1.0f / sw[0];
    a.x *= inv; a.y *= inv; a.z *= inv; a.w *= inv;
    c.x *= inv; c.y *= inv; c.z *= inv; c.w *= inv;
    reinterpret_cast<float4*>(r)[t] = a;
    reinterpret_cast<float4*>(r)[t + 256] = c;
}

// ---------------- Launch ---------------------------------------------------
extern "C" void kernel_launch(void* const* d_in, const int* in_sizes, int n_in,
                              void* d_out, int out_size) {
    const float* x      = (const float*)d_in[0];
    const float* gamma  = (const float*)d_in[1];
    const float* dist   = (const float*)d_in[2];
    const float* ln1_w  = (const float*)d_in[3];
    const float* ln1_b  = (const float*)d_in[4];
    const float* qkv_w  = (const float*)d_in[5];
    const float* qkv_b  = (const float*)d_in[6];
    const float* proj_w = (const float*)d_in[7];
    const float* proj_b = (const float*)d_in[8];
    const float* ln2_w  = (const float*)d_in[9];
    const float* ln2_b  = (const float*)d_in[10];
    const float* mlp_w1 = (const float*)d_in[11];
    const float* mlp_b1 = (const float*)d_in[12];
    const float* mlp_w2 = (const float*)d_in[13];
    const float* mlp_b2 = (const float*)d_in[14];
    float* out = (float*)d_out;

    float *p_h, *p_qkv, *p_kT, *p_sc, *p_attn, *p_x1, *p_mid;
    cudaGetSymbolAddress((void**)&p_h, g_h);
    cudaGetSymbolAddress((void**)&p_qkv, g_qkv);
    cudaGetSymbolAddress((void**)&p_kT, g_kT);
    cudaGetSymbolAddress((void**)&p_sc, g_scores);
    cudaGetSymbolAddress((void**)&p_attn, g_attn);
    cudaGetSymbolAddress((void**)&p_x1, g_x1);
    cudaGetSymbolAddress((void**)&p_mid, g_mid);

    const size_t qkvRowB = (size_t)NN * (3 * DD);   // per-batch stride in qkv
    const size_t scZ = (size_t)NN * NN;             // per-(b,h) score matrix

    // 1) LN1: x -> g_h
    ln_kernel<<<MTOK, 256>>>(x, ln1_w, ln1_b, p_h);

    // 2) QKV GEMM: [4096,1024]@[1024,3072]+b -> g_qkv
    tf32gemm_kernel<128, 128, 16><<<dim3(3 * DD / 128, MTOK / 128, 1), 256>>>(
        p_h, qkv_w, p_qkv, MTOK, 3 * DD, DD, DD, 3 * DD, 3 * DD,
        0, 0, 0, 0, 0, 0, qkv_b, nullptr, 0, 0, nullptr, nullptr, 1.0f);

    // 3) Transpose K per head -> g_kT [z][64][2048]
    transpose_k_kernel<<<dim3(NN / 32, DHH / 32, BB * HH), dim3(32, 8)>>>(
        p_qkv, p_kT);

    // 4) Scores GEMM (batched over 32 heads): q @ kT, fused scale - gamma*dist
    tf32gemm_kernel<128, 128, 16><<<dim3(NN / 128, NN / 128, BB * HH), 256>>>(
        p_qkv /*q base, col 0*/, p_kT, p_sc, NN, NN, DHH, 3 * DD, NN, NN,
        /*aOuter*/ qkvRowB, /*aInner*/ (size_t)DHH,
        /*bOuter*/ (size_t)HH * DHH * NN, /*bInner*/ (size_t)DHH * NN,
        /*cOuter*/ (size_t)HH * scZ, /*cInner*/ scZ,
        nullptr, nullptr, 0, 0, gamma, dist, SCORE_SCALE);

    // 5) Softmax in place
    softmax_kernel<<<dim3(NN, BB * HH), 256>>>(p_sc);

    // 6) attn @ V (batched): [2048,2048]@[2048,64] -> g_attn[b*N+n][h*64+dh]
    tf32gemm_kernel<128, 64, 16><<<dim3(1, NN / 128, BB * HH), 256>>>(
        p_sc, p_qkv + 2 * DD /*v base*/, p_attn, NN, DHH, NN, NN, 3 * DD, DD,
        /*aOuter*/ (size_t)HH * scZ, /*aInner*/ scZ,
        /*bOuter*/ qkvRowB, /*bInner*/ (size_t)DHH,
        /*cOuter*/ (size_t)NN * DD, /*cInner*/ (size_t)DHH,
        nullptr, nullptr, 0, 0, nullptr, nullptr, 1.0f);

    // 7) Proj GEMM + residual x -> g_x1
    tf32gemm_kernel<128, 128, 16><<<dim3(DD / 128, MTOK / 128, 1), 256>>>(
        p_attn, proj_w, p_x1, MTOK, DD, DD, DD, DD, DD,
        0, 0, 0, 0, 0, 0, proj_b, x, DD, 0, nullptr, nullptr, 1.0f);

    // 8) LN2: g_x1 -> g_h
    ln_kernel<<<MTOK, 256>>>(p_x1, ln2_w, ln2_b, p_h);

    // 9) MLP1 GEMM + exact GELU -> g_mid
    tf32gemm_kernel<128, 128, 16><<<dim3(DFF / 128, MTOK / 128, 1), 256>>>(
        p_h, mlp_w1, p_mid, MTOK, DFF, DD, DD, DFF, DFF,
        0, 0, 0, 0, 0, 0, mlp_b1, nullptr, 0, 1, nullptr, nullptr, 1.0f);

    // 10) MLP2 GEMM + residual g_x1 -> out
    tf32gemm_kernel<128, 128, 16><<<dim3(DD / 128, MTOK / 128, 1), 256>>>(
        p_mid, mlp_w2, out, MTOK, DD, DFF, DFF, DD, DD,
        0, 0, 0, 0, 0, 0, mlp_b2, p_x1, DD, 0, nullptr, nullptr, 1.0f);
}

// round 13
// speedup vs baseline: 1.1362x; 1.1362x over previous
#include <cuda_runtime.h>
#include <cstdint>
#include <cstddef>
#include <math.h>

// Problem constants
#define BB 2
#define NN 2048
#define DD 1024
#define HH 16
#define DHH 64
#define DFF 4096
#define MTOK 4096            // B*N tokens
#define SCORE_SCALE 0.03125f // D^-0.5 = 1/32

// ---------------- Scratch (static device globals; no cudaMalloc allowed) ----
__device__ float g_h[(size_t)MTOK * DD];                  // LN output (reused)
__device__ float g_qkv[(size_t)MTOK * (3 * DD)];          // QKV projection
__device__ float g_attn[(size_t)MTOK * DD];               // attn out, [b*N+n][h*64+dh]
__device__ float g_x1[(size_t)MTOK * DD];                 // x + proj(attn)
__device__ float g_mid[(size_t)MTOK * DFF];               // MLP hidden

__device__ __forceinline__ float gelu_exact(float v) {
    return 0.5f * v * (1.0f + erff(v * 0.70710678118654752f));
}

__device__ __forceinline__ uint32_t tf32_bits(float x) {
    uint32_t u;
    asm("cvt.rna.tf32.f32 %0, %1;" : "=r"(u) : "f"(x));
    return u;
}

__device__ __forceinline__ void mma_tf32(float* c, const uint32_t* a,
                                         const uint32_t* b) {
    asm volatile(
        "mma.sync.aligned.m16n8k8.row.col.f32.tf32.tf32.f32 "
        "{%0,%1,%2,%3}, {%4,%5,%6,%7}, {%8,%9}, {%0,%1,%2,%3};"
        : "+f"(c[0]), "+f"(c[1]), "+f"(c[2]), "+f"(c[3])
        : "r"(a[0]), "r"(a[1]), "r"(a[2]), "r"(a[3]), "r"(b[0]), "r"(b[1]));
}

__device__ __forceinline__ void cp_async16(uint32_t saddr, const void* gptr) {
    asm volatile("cp.async.cg.shared.global [%0], [%1], 16;"
                 :: "r"(saddr), "l"(gptr));
}
__device__ __forceinline__ void cp_commit() {
    asm volatile("cp.async.commit_group;");
}
template <int N>
__device__ __forceinline__ void cp_wait() {
    asm volatile("cp.async.wait_group %0;" :: "n"(N));
}

// ---------------- TF32 tensor-core GEMM with fused epilogue ----------------
// (verified passing in R4 at 1383us total)
template <int BM, int BN, int BK>
__global__ void __launch_bounds__(256, 2)
tf32gemm_kernel(const float* __restrict__ A, const float* __restrict__ Bm,
                float* __restrict__ C,
                int M, int Ncols, int K, int lda, int ldb, int ldc,
                size_t aOuter, size_t aInner, size_t bOuter, size_t bInner,
                size_t cOuter, size_t cInner,
                const float* __restrict__ bias,
                const float* __restrict__ res, int ldres, int act,
                float scale) {
    constexpr int THREADS = 256;
    constexpr int WARPS_N = BN / 32;
    constexpr int WARPS_M = 8 / WARPS_N;
    constexpr int WM = BM / WARPS_M;
    constexpr int MI = WM / 16;
    constexpr int APAD = 4;
    constexpr int BPAD = 8;

    const int z = blockIdx.z;
    A  += (size_t)(z >> 4) * aOuter + (size_t)(z & 15) * aInner;
    Bm += (size_t)(z >> 4) * bOuter + (size_t)(z & 15) * bInner;
    C  += (size_t)(z >> 4) * cOuter + (size_t)(z & 15) * cInner;

    __shared__ float As[2][BM][BK + APAD];
    __shared__ float Bs[2][BK][BN + BPAD];

    const int tid = threadIdx.x;
    const int wid = tid >> 5;
    const int lane = tid & 31;
    const int grp = lane >> 2;
    const int qid = lane & 3;
    const int warp_m0 = (wid % WARPS_M) * WM;
    const int warp_n0 = (wid / WARPS_M) * 32;
    const int m0 = blockIdx.y * BM;
    const int n0 = blockIdx.x * BN;

    float acc[MI][4][4];
#pragma unroll
    for (int i = 0; i < MI; i++)
#pragma unroll
        for (int j = 0; j < 4; j++)
#pragma unroll
            for (int r = 0; r < 4; r++) acc[i][j][r] = 0.0f;

    constexpr int A_V4 = BM * BK / 4;
    constexpr int B_V4 = BK * BN / 4;
    constexpr int A_LD = (A_V4 + THREADS - 1) / THREADS;
    constexpr int B_LD = (B_V4 + THREADS - 1) / THREADS;

    int a_m[A_LD], a_k[A_LD], b_k[B_LD], b_n[B_LD];
#pragma unroll
    for (int u = 0; u < A_LD; u++) {
        int i = tid + u * THREADS;
        a_m[u] = i / (BK / 4);
        a_k[u] = (i % (BK / 4)) * 4;
    }
#pragma unroll
    for (int u = 0; u < B_LD; u++) {
        int i = tid + u * THREADS;
        b_k[u] = i / (BN / 4);
        b_n[u] = (i % (BN / 4)) * 4;
    }

    const int KT = K / BK;

    auto load_tile = [&](int buf, int k0) {
#pragma unroll
        for (int u = 0; u < A_LD; u++) {
            if (tid + u * THREADS < A_V4) {
                uint32_t sa = (uint32_t)__cvta_generic_to_shared(
                    &As[buf][a_m[u]][a_k[u]]);
                cp_async16(sa, &A[(size_t)(m0 + a_m[u]) * lda + k0 + a_k[u]]);
            }
        }
#pragma unroll
        for (int u = 0; u < B_LD; u++) {
            if (tid + u * THREADS < B_V4) {
                uint32_t sb = (uint32_t)__cvta_generic_to_shared(
                    &Bs[buf][b_k[u]][b_n[u]]);
                cp_async16(sb, &Bm[(size_t)(k0 + b_k[u]) * ldb + n0 + b_n[u]]);
            }
        }
    };

    load_tile(0, 0);
    cp_commit();

    for (int kt = 0; kt < KT; kt++) {
        const int cur = kt & 1;
        const int nxt = cur ^ 1;

        if (kt + 1 < KT) {
            load_tile(nxt, (kt + 1) * BK);
            cp_commit();
            cp_wait<1>();
        } else {
            cp_wait<0>();
        }
        __syncthreads();

#pragma unroll
        for (int kh = 0; kh < BK; kh += 8) {
            uint32_t af[MI][4];
            uint32_t bf[4][2];
#pragma unroll
            for (int mi = 0; mi < MI; mi++) {
                const int mr = warp_m0 + mi * 16 + grp;
                af[mi][0] = tf32_bits(As[cur][mr][kh + qid]);
                af[mi][1] = tf32_bits(As[cur][mr + 8][kh + qid]);
                af[mi][2] = tf32_bits(As[cur][mr][kh + qid + 4]);
                af[mi][3] = tf32_bits(As[cur][mr + 8][kh + qid + 4]);
            }
#pragma unroll
            for (int ni = 0; ni < 4; ni++) {
                const int nc = warp_n0 + ni * 8 + grp;
                bf[ni][0] = tf32_bits(Bs[cur][kh + qid][nc]);
                bf[ni][1] = tf32_bits(Bs[cur][kh + qid + 4][nc]);
            }
#pragma unroll
            for (int mi = 0; mi < MI; mi++)
#pragma unroll
                for (int ni = 0; ni < 4; ni++)
                    mma_tf32(acc[mi][ni], af[mi], bf[ni]);
        }
        __syncthreads();
    }

#pragma unroll
    for (int mi = 0; mi < MI; mi++) {
#pragma unroll
        for (int ni = 0; ni < 4; ni++) {
            const int col = n0 + warp_n0 + ni * 8 + 2 * qid;
#pragma unroll
            for (int half = 0; half < 2; half++) {
                const int row = m0 + warp_m0 + mi * 16 + grp + half * 8;
                float2 v = make_float2(acc[mi][ni][half * 2],
                                       acc[mi][ni][half * 2 + 1]);
                if (bias != nullptr) {
                    float2 bb = *reinterpret_cast<const float2*>(&bias[col]);
                    v.x += bb.x; v.y += bb.y;
                }
                if (act) {
                    v.x = gelu_exact(v.x);
                    v.y = gelu_exact(v.y);
                }
                if (res != nullptr) {
                    float2 rr = *reinterpret_cast<const float2*>(
                        &res[(size_t)row * ldres + col]);
                    v.x += rr.x; v.y += rr.y;
                }
                *reinterpret_cast<float2*>(&C[(size_t)row * ldc + col]) = v;
            }
        }
    }
}

// ---------------- Flash attention: fused scores+bias+softmax+attnV ---------
// Grid: (16 row-tiles, 32 z=b*16+h). Block 256 = 8 warps; warp owns 16 rows.
// smem: K[2][128][68] | V[2][128][72] (dynamic, 143360 B).
// Kb stride 68 (s=4 mod 32): K-frag bank 4*grp+qid -> 32-bank permutation.
// Vb stride 72 (s=8 mod 32): V-frag bank 8*qid+grp -> 32-bank permutation.
// Q staging reads share the K-frag pattern -> also conflict-free.
#define KSTR (DHH + 4)     // 68
#define VSTR (DHH + 8)     // 72
#define FLASH_SMEM ((2 * 128 * KSTR + 2 * 128 * VSTR) * 4)

__global__ void __launch_bounds__(256, 1)
flash_attn_kernel(const float* __restrict__ qkv, const float* __restrict__ gamma,
                  const float* __restrict__ dist, float* __restrict__ attn_out) {
    extern __shared__ float fsm[];
    float* Kb = fsm;                       // [2][128][KSTR]
    float* Vb = fsm + 2 * 128 * KSTR;      // [2][128][VSTR]

    const int z = blockIdx.y;
    const int bb = z >> 4, hh = z & 15;
    const int mt = blockIdx.x;
    const int tid = threadIdx.x;
    const int wid = tid >> 5;
    const int lane = tid & 31;
    const int grp = lane >> 2;
    const int qid = lane & 3;
    const int warp_m0 = wid * 16;

    const float* qbase = qkv + (size_t)bb * NN * (3 * DD) + hh * DHH;
    const float* kbase = qbase + DD;
    const float* vbase = qbase + 2 * DD;

    // ---- Stage Q tile (128x64) through K buffer 0, read A-fragments ----
#pragma unroll
    for (int u = 0; u < 8; u++) {
        int i = tid + u * 256;             // 0..2047
        int r = i >> 4;
        int c = (i & 15) * 4;
        uint32_t sa = (uint32_t)__cvta_generic_to_shared(&Kb[r * KSTR + c]);
        cp_async16(sa, qbase + (size_t)(mt * 128 + r) * (3 * DD) + c);
    }
    cp_commit();
    cp_wait<0>();
    __syncthreads();

    uint32_t qf[8][4];
#pragma unroll
    for (int ks = 0; ks < 8; ks++) {
        const float* q0 = &Kb[(warp_m0 + grp) * KSTR + ks * 8];
        const float* q1 = &Kb[(warp_m0 + grp + 8) * KSTR + ks * 8];
        qf[ks][0] = tf32_bits(q0[qid]);
        qf[ks][1] = tf32_bits(q1[qid]);
        qf[ks][2] = tf32_bits(q0[qid + 4]);
        qf[ks][3] = tf32_bits(q1[qid + 4]);
    }
    __syncthreads();   // everyone done reading Q before K reload

    auto loadKV = [&](int buf, int jt) {
#pragma unroll
        for (int u = 0; u < 8; u++) {
            int i = tid + u * 256;
            int r = i >> 4;
            int c = (i & 15) * 4;
            size_t grow = (size_t)(jt * 128 + r) * (3 * DD) + c;
            uint32_t sk = (uint32_t)__cvta_generic_to_shared(
                &Kb[(buf * 128 + r) * KSTR + c]);
            uint32_t sv = (uint32_t)__cvta_generic_to_shared(
                &Vb[(buf * 128 + r) * VSTR + c]);
            cp_async16(sk, kbase + grow);
            cp_async16(sv, vbase + grow);
        }
    };

    loadKV(0, 0);
    cp_commit();

    const float g = gamma[z];
    const int row0 = mt * 128 + warp_m0 + grp;   // global row (0..2047)
    const int row1 = row0 + 8;

    float m_run0 = -1e30f, m_run1 = -1e30f;
    float l_run0 = 0.0f, l_run1 = 0.0f;
    float oacc[8][4];
#pragma unroll
    for (int dt = 0; dt < 8; dt++)
#pragma unroll
        for (int r = 0; r < 4; r++) oacc[dt][r] = 0.0f;

    for (int jt = 0; jt < 16; jt++) {
        const int cur = jt & 1;
        if (jt + 1 < 16) {
            loadKV(cur ^ 1, jt + 1);
            cp_commit();
            cp_wait<1>();
        } else {
            cp_wait<0>();
        }
        __syncthreads();

        // ---- S = Q @ K^T for this 128-col tile ----
        float sacc[16][4];
#pragma unroll
        for (int ni = 0; ni < 16; ni++)
#pragma unroll
            for (int r = 0; r < 4; r++) sacc[ni][r] = 0.0f;

#pragma unroll
        for (int ks = 0; ks < 8; ks++) {
#pragma unroll
            for (int ni = 0; ni < 16; ni++) {
                const float* kr = &Kb[(cur * 128 + ni * 8 + grp) * KSTR + ks * 8];
                uint32_t bf[2];
                bf[0] = tf32_bits(kr[qid]);
                bf[1] = tf32_bits(kr[qid + 4]);
                mma_tf32(sacc[ni], qf[ks], bf);
            }
        }

        // ---- scale + distance bias; tile row-max ----
        float tmax0 = -1e30f, tmax1 = -1e30f;
#pragma unroll
        for (int ni = 0; ni < 16; ni++) {
            const int col = jt * 128 + ni * 8 + 2 * qid;
            float2 d0 = *reinterpret_cast<const float2*>(
                &dist[(size_t)row0 * NN + col]);
            float2 d1 = *reinterpret_cast<const float2*>(
                &dist[(size_t)row1 * NN + col]);
            sacc[ni][0] = sacc[ni][0] * SCORE_SCALE - g * d0.x;
            sacc[ni][1] = sacc[ni][1] * SCORE_SCALE - g * d0.y;
            sacc[ni][2] = sacc[ni][2] * SCORE_SCALE - g * d1.x;
            sacc[ni][3] = sacc[ni][3] * SCORE_SCALE - g * d1.y;
            tmax0 = fmaxf(tmax0, fmaxf(sacc[ni][0], sacc[ni][1]));
            tmax1 = fmaxf(tmax1, fmaxf(sacc[ni][2], sacc[ni][3]));
        }
        tmax0 = fmaxf(tmax0, __shfl_xor_sync(0xffffffffu, tmax0, 1));
        tmax0 = fmaxf(tmax0, __shfl_xor_sync(0xffffffffu, tmax0, 2));
        tmax1 = fmaxf(tmax1, __shfl_xor_sync(0xffffffffu, tmax1, 1));
        tmax1 = fmaxf(tmax1, __shfl_xor_sync(0xffffffffu, tmax1, 2));

        const float mnew0 = fmaxf(m_run0, tmax0);
        const float mnew1 = fmaxf(m_run1, tmax1);
        const float corr0 = __expf(m_run0 - mnew0);
        const float corr1 = __expf(m_run1 - mnew1);

        // ---- P = exp(S - m), row sums ----
        float rs0 = 0.0f, rs1 = 0.0f;
#pragma unroll
        for (int ni = 0; ni < 16; ni++) {
            sacc[ni][0] = __expf(sacc[ni][0] - mnew0);
            sacc[ni][1] = __expf(sacc[ni][1] - mnew0);
            sacc[ni][2] = __expf(sacc[ni][2] - mnew1);
            sacc[ni][3] = __expf(sacc[ni][3] - mnew1);
            rs0 += sacc[ni][0] + sacc[ni][1];
            rs1 += sacc[ni][2] + sacc[ni][3];
        }
        rs0 += __shfl_xor_sync(0xffffffffu, rs0, 1);
        rs0 += __shfl_xor_sync(0xffffffffu, rs0, 2);
        rs1 += __shfl_xor_sync(0xffffffffu, rs1, 1);
        rs1 += __shfl_xor_sync(0xffffffffu, rs1, 2);

        l_run0 = l_run0 * corr0 + rs0;
        l_run1 = l_run1 * corr1 + rs1;
        m_run0 = mnew0;
        m_run1 = mnew1;

        // ---- rescale O ----
#pragma unroll
        for (int dt = 0; dt < 8; dt++) {
            oacc[dt][0] *= corr0;
            oacc[dt][1] *= corr0;
            oacc[dt][2] *= corr1;
            oacc[dt][3] *= corr1;
        }

        // ---- O += P @ V : convert P C-layout -> A-layout via shuffles ----
        const int src_lo = (lane & ~3) | (qid >> 1);
        const int src_hi = src_lo + 2;
        const int sel = qid & 1;
#pragma unroll
        for (int ni = 0; ni < 16; ni++) {
            float c0 = sacc[ni][0], c1 = sacc[ni][1];
            float c2 = sacc[ni][2], c3 = sacc[ni][3];
            float e0 = __shfl_sync(0xffffffffu, c0, src_lo);
            float e1 = __shfl_sync(0xffffffffu, c1, src_lo);
            float f0 = __shfl_sync(0xffffffffu, c0, src_hi);
            float f1 = __shfl_sync(0xffffffffu, c1, src_hi);
            float g0 = __shfl_sync(0xffffffffu, c2, src_lo);
            float g1 = __shfl_sync(0xffffffffu, c3, src_lo);
            float h0 = __shfl_sync(0xffffffffu, c2, src_hi);
            float h1 = __shfl_sync(0xffffffffu, c3, src_hi);
            uint32_t pa[4];
            pa[0] = tf32_bits(sel ? e1 : e0);
            pa[1] = tf32_bits(sel ? g1 : g0);
            pa[2] = tf32_bits(sel ? f1 : f0);
            pa[3] = tf32_bits(sel ? h1 : h0);
            const float* vr0 = &Vb[(cur * 128 + ni * 8 + qid) * VSTR];
            const float* vr1 = &Vb[(cur * 128 + ni * 8 + qid + 4) * VSTR];
#pragma unroll
            for (int dt = 0; dt < 8; dt++) {
                uint32_t bv[2];
                bv[0] = tf32_bits(vr0[dt * 8 + grp]);
                bv[1] = tf32_bits(vr1[dt * 8 + grp]);
                mma_tf32(oacc[dt], pa, bv);
            }
        }
        __syncthreads();   // cur buffer free before next prefetch overwrites
    }

    // ---- Finalize: O / l, write to g_attn [token][h*64+d] ----
    const float inv0 = 1.0f / l_run0;
    const float inv1 = 1.0f / l_run1;
    float* out0 = attn_out + (size_t)(bb * NN + row0) * DD + hh * DHH;
    float* out1 = attn_out + (size_t)(bb * NN + row1) * DD + hh * DHH;
#pragma unroll
    for (int dt = 0; dt < 8; dt++) {
        const int dcol = dt * 8 + 2 * qid;
        *reinterpret_cast<float2*>(out0 + dcol) =
            make_float2(oacc[dt][0] * inv0, oacc[dt][1] * inv0);
        *reinterpret_cast<float2*>(out1 + dcol) =
            make_float2(oacc[dt][2] * inv1, oacc[dt][3] * inv1);
    }
}

// ---------------- LayerNorm: one block per row of 1024 ---------------------
__global__ void ln_kernel(const float* __restrict__ x, const float* __restrict__ w,
                          const float* __restrict__ b, float* __restrict__ o) {
    const int row = blockIdx.x;
    const int t = threadIdx.x;
    const float4* xr = reinterpret_cast<const float4*>(x + (size_t)row * DD);
    float4 v = xr[t];
    float s = v.x + v.y + v.z + v.w;
    float q = v.x * v.x + v.y * v.y + v.z * v.z + v.w * v.w;
#pragma unroll
    for (int off = 16; off; off >>= 1) {
        s += __shfl_xor_sync(0xffffffffu, s, off);
        q += __shfl_xor_sync(0xffffffffu, q, off);
    }
    __shared__ float ss[8], qq[8];
    if ((t & 31) == 0) { ss[t >> 5] = s; qq[t >> 5] = q; }
    __syncthreads();
    if (t < 32) {
        s = (t < 8) ? ss[t] : 0.0f;
        q = (t < 8) ? qq[t] : 0.0f;
#pragma unroll
        for (int off = 4; off; off >>= 1) {
            s += __shfl_xor_sync(0xffffffffu, s, off);
            q += __shfl_xor_sync(0xffffffffu, q, off);
        }
        if (t == 0) { ss[0] = s; qq[0] = q; }
    }
    __syncthreads();
    s = ss[0]; q = qq[0];
    const float mu = s * (1.0f / DD);
    const float var = q * (1.0f / DD) - mu * mu;
    const float inv = rsqrtf(var + 1e-5f);
    float4 wv = reinterpret_cast<const float4*>(w)[t];
    float4 bv = reinterpret_cast<const float4*>(b)[t];
    float4 r;
    r.x = (v.x - mu) * inv * wv.x + bv.x;
    r.y = (v.y - mu) * inv * wv.y + bv.y;
    r.z = (v.z - mu) * inv * wv.z + bv.z;
    r.w = (v.w - mu) * inv * wv.w + bv.w;
    reinterpret_cast<float4*>(o + (size_t)row * DD)[t] = r;
}

// ---------------- Launch ---------------------------------------------------
extern "C" void kernel_launch(void* const* d_in, const int* in_sizes, int n_in,
                              void* d_out, int out_size) {
    const float* x      = (const float*)d_in[0];
    const float* gamma  = (const float*)d_in[1];
    const float* dist   = (const float*)d_in[2];
    const float* ln1_w  = (const float*)d_in[3];
    const float* ln1_b  = (const float*)d_in[4];
    const float* qkv_w  = (const float*)d_in[5];
    const float* qkv_b  = (const float*)d_in[6];
    const float* proj_w = (const float*)d_in[7];
    const float* proj_b = (const float*)d_in[8];
    const float* ln2_w  = (const float*)d_in[9];
    const float* ln2_b  = (const float*)d_in[10];
    const float* mlp_w1 = (const float*)d_in[11];
    const float* mlp_b1 = (const float*)d_in[12];
    const float* mlp_w2 = (const float*)d_in[13];
    const float* mlp_b2 = (const float*)d_in[14];
    float* out = (float*)d_out;

    float *p_h, *p_qkv, *p_attn, *p_x1, *p_mid;
    cudaGetSymbolAddress((void**)&p_h, g_h);
    cudaGetSymbolAddress((void**)&p_qkv, g_qkv);
    cudaGetSymbolAddress((void**)&p_attn, g_attn);
    cudaGetSymbolAddress((void**)&p_x1, g_x1);
    cudaGetSymbolAddress((void**)&p_mid, g_mid);

    // Unconditional (no static guards allowed in kernel_launch).
    cudaFuncSetAttribute(flash_attn_kernel,
                         cudaFuncAttributeMaxDynamicSharedMemorySize,
                         FLASH_SMEM);

    // 1) LN1: x -> g_h
    ln_kernel<<<MTOK, 256>>>(x, ln1_w, ln1_b, p_h);

    // 2) QKV GEMM: [4096,1024]@[1024,3072]+b -> g_qkv
    tf32gemm_kernel<128, 128, 16><<<dim3(3 * DD / 128, MTOK / 128, 1), 256>>>(
        p_h, qkv_w, p_qkv, MTOK, 3 * DD, DD, DD, 3 * DD, 3 * DD,
        0, 0, 0, 0, 0, 0, qkv_b, nullptr, 0, 0, 1.0f);

    // 3) Fused flash attention -> g_attn
    flash_attn_kernel<<<dim3(NN / 128, BB * HH), 256, FLASH_SMEM>>>(
        p_qkv, gamma, dist, p_attn);

    // 4) Proj GEMM + residual x -> g_x1
    tf32gemm_kernel<128, 128, 16><<<dim3(DD / 128, MTOK / 128, 1), 256>>>(
        p_attn, proj_w, p_x1, MTOK, DD, DD, DD, DD, DD,
        0, 0, 0, 0, 0, 0, proj_b, x, DD, 0, 1.0f);

    // 5) LN2: g_x1 -> g_h
    ln_kernel<<<MTOK, 256>>>(p_x1, ln2_w, ln2_b, p_h);

    // 6) MLP1 GEMM + exact GELU -> g_mid
    tf32gemm_kernel<128, 128, 16><<<dim3(DFF / 128, MTOK / 128, 1), 256>>>(
        p_h, mlp_w1, p_mid, MTOK, DFF, DD, DD, DFF, DFF,
        0, 0, 0, 0, 0, 0, mlp_b1, nullptr, 0, 1, 1.0f);

    // 7) MLP2 GEMM + residual g_x1 -> out
    tf32gemm_kernel<128, 128, 16><<<dim3(DD / 128, MTOK / 128, 1), 256>>>(
        p_mid, mlp_w2, out, MTOK, DD, DFF, DFF, DD, DD,
        0, 0, 0, 0, 0, 0, mlp_b2, p_x1, DD, 0, 1.0f);
}